// round 1
// baseline (speedup 1.0000x reference)
#include <cuda_runtime.h>
#include <math.h>

// ---------------- problem constants ----------------
#define BB 4
#define TT 128
#define NBT 512            // B*T
#define NN 64
#define DD 128
#define HH 4
#define DHH 32
#define LL 3
#define D4 512
#define NROWS (NBT*NN)     // 32768
#define MAXE 4096

// ---------------- scratch (device globals; no allocation) ----------------
__device__ float g_Z   [NROWS*DD];
__device__ float g_Hn  [NROWS*DD];
__device__ float g_Hmix[NROWS*DD];
__device__ float g_Xq  [NROWS*DD];
__device__ float g_Xv  [NROWS*DD];
__device__ float g_Y   [NROWS*DD];
__device__ float g_U   [NROWS*DD];
__device__ float g_M1  [NROWS*D4];
__device__ float g_A   [NN*NN];
__device__ float g_logA0[MAXE];
__device__ int   g_rowptr[NN+1];

// ---------------- generic tiled SGEMM with fused epilogue ----------------
// C[M,N] = act( A[M,K] @ B[K,N] + bias ) + add1 + add2
// act: 0 = none, 1 = silu (applied after bias, before adds)
__global__ __launch_bounds__(256) void sgemm_kernel(
    const float* __restrict__ A, const float* __restrict__ B, float* __restrict__ C,
    int M, int K, int N,
    const float* __restrict__ bias, const float* __restrict__ add1,
    const float* __restrict__ add2, int act)
{
    __shared__ float As[16][64];   // As[k][m]
    __shared__ float Bs[16][64];   // Bs[k][n]
    const int bm = blockIdx.y * 64;
    const int bn = blockIdx.x * 64;
    const int tid = threadIdx.x;
    const int tx = tid & 15;       // N direction
    const int ty = tid >> 4;       // M direction

    const int am  = tid >> 2;         // 0..63  (row within A tile)
    const int ak  = (tid & 3) * 4;    // 0,4,8,12
    const int bk  = tid >> 4;         // 0..15
    const int bn4 = (tid & 15) * 4;   // 0..60

    float acc[4][4] = {};

    for (int k0 = 0; k0 < K; k0 += 16) {
        float4 a4 = *(const float4*)(A + (size_t)(bm + am) * K + k0 + ak);
        As[ak + 0][am] = a4.x;
        As[ak + 1][am] = a4.y;
        As[ak + 2][am] = a4.z;
        As[ak + 3][am] = a4.w;
        *(float4*)&Bs[bk][bn4] = *(const float4*)(B + (size_t)(k0 + bk) * N + bn + bn4);
        __syncthreads();
        #pragma unroll
        for (int k = 0; k < 16; k++) {
            float4 av = *(const float4*)&As[k][ty * 4];
            float4 bv = *(const float4*)&Bs[k][tx * 4];
            float ar[4] = {av.x, av.y, av.z, av.w};
            float br[4] = {bv.x, bv.y, bv.z, bv.w};
            #pragma unroll
            for (int i = 0; i < 4; i++)
                #pragma unroll
                for (int j = 0; j < 4; j++)
                    acc[i][j] += ar[i] * br[j];
        }
        __syncthreads();
    }

    #pragma unroll
    for (int i = 0; i < 4; i++) {
        const int r = bm + ty * 4 + i;
        const size_t ro = (size_t)r * N;
        #pragma unroll
        for (int j = 0; j < 4; j++) {
            const int c = bn + tx * 4 + j;
            float v = acc[i][j];
            if (bias) v += bias[c];
            if (act)  v = v / (1.0f + expf(-v));    // silu
            if (add1) v += add1[ro + c];
            if (add2) v += add2[ro + c];
            C[ro + c] = v;
        }
    }
}

// ---------------- LayerNorm (warp per row of 128) ----------------
__global__ void ln_kernel(const float* __restrict__ X, float* __restrict__ O,
                          const float* __restrict__ g, const float* __restrict__ b)
{
    int r = blockIdx.x * (blockDim.x >> 5) + (threadIdx.x >> 5);
    if (r >= NROWS) return;
    int lane = threadIdx.x & 31;
    const float* x = X + (size_t)r * DD;
    float v[4], s = 0.f, ss = 0.f;
    #pragma unroll
    for (int q = 0; q < 4; q++) { v[q] = x[lane + 32*q]; s += v[q]; ss += v[q]*v[q]; }
    #pragma unroll
    for (int o = 16; o; o >>= 1) {
        s  += __shfl_xor_sync(0xffffffffu, s,  o);
        ss += __shfl_xor_sync(0xffffffffu, ss, o);
    }
    float mu  = s  * (1.f/128.f);
    float var = ss * (1.f/128.f) - mu * mu;
    float inv = rsqrtf(var + 1e-5f);
    float* o = O + (size_t)r * DD;
    #pragma unroll
    for (int q = 0; q < 4; q++) {
        int d = lane + 32*q;
        o[d] = (v[q] - mu) * inv * g[d] + b[d];
    }
}

// ---------------- NodeGate (squeeze-excite) + LN2 fused, warp per row ----------------
__global__ void gate_ln2_kernel(float* __restrict__ U, float* __restrict__ Out,
    const float* __restrict__ g1w, const float* __restrict__ g1b,
    const float* __restrict__ g2w, const float* __restrict__ g2bp,
    const float* __restrict__ ln2g, const float* __restrict__ ln2b)
{
    int r = blockIdx.x * (blockDim.x >> 5) + (threadIdx.x >> 5);
    if (r >= NROWS) return;
    int lane = threadIdx.x & 31;
    float* u = U + (size_t)r * DD;
    float v[4], s = 0.f, ss = 0.f;
    #pragma unroll
    for (int q = 0; q < 4; q++) { v[q] = u[lane + 32*q]; s += v[q]; ss += v[q]*v[q]; }
    #pragma unroll
    for (int o = 16; o; o >>= 1) {
        s  += __shfl_xor_sync(0xffffffffu, s,  o);
        ss += __shfl_xor_sync(0xffffffffu, ss, o);
    }
    float mu  = s  * (1.f/128.f);
    float var = ss * (1.f/128.f) - mu * mu;
    // gate: g = sigmoid( sum_d silu(mu*g1w[d]+g1b[d]) * g2w[d] + g2b )
    float acc = 0.f;
    #pragma unroll
    for (int q = 0; q < 4; q++) {
        int d = lane + 32*q;
        float t = mu * g1w[d] + g1b[d];
        acc += (t / (1.f + expf(-t))) * g2w[d];
    }
    #pragma unroll
    for (int o = 16; o; o >>= 1) acc += __shfl_xor_sync(0xffffffffu, acc, o);
    float gate = 1.f / (1.f + expf(-(acc + g2bp[0])));
    // scaled stats: mean' = g*mu, var' = g^2*var
    float mu2  = mu * gate;
    float inv  = rsqrtf(var * gate * gate + 1e-5f);
    float* o = Out + (size_t)r * DD;
    #pragma unroll
    for (int q = 0; q < 4; q++) {
        int d = lane + 32*q;
        float uv = v[q] * gate;
        u[d] = uv;                                    // gated U (residual path)
        o[d] = (uv - mu2) * inv * ln2g[d] + ln2b[d];  // LN2 output
    }
}

// ---------------- Hmix = A @ Hn  (per bt; both tiles in smem) ----------------
__global__ __launch_bounds__(256) void hmix_kernel(const float* __restrict__ A,
                                                   const float* __restrict__ Hn,
                                                   float* __restrict__ Hmix)
{
    __shared__ float sA[NN*NN];     // 16 KB
    __shared__ float sH[NN*DD];     // 32 KB
    int bt = blockIdx.x;
    for (int t = threadIdx.x; t < NN*NN; t += blockDim.x) sA[t] = A[t];
    const float* Hb = Hn + (size_t)bt * NN * DD;
    for (int t = threadIdx.x; t < NN*DD; t += blockDim.x) sH[t] = Hb[t];
    __syncthreads();
    int d  = threadIdx.x & 127;
    for (int i = threadIdx.x >> 7; i < NN; i += 2) {
        float acc = 0.f;
        #pragma unroll 8
        for (int j = 0; j < NN; j++) acc += sA[i*NN + j] * sH[j*DD + d];
        Hmix[((size_t)bt * NN + i) * DD + d] = acc;
    }
}

// ---------------- blended adjacency A ----------------
__global__ void adj_kernel(const float* __restrict__ A0, const float* __restrict__ P,
                           const float* __restrict__ Qm, const float* __restrict__ alphap,
                           float* __restrict__ A)
{
    int i = blockIdx.x, j = threadIdx.x;
    float a0 = A0[i*NN + j];
    float dot = 0.f;
    #pragma unroll
    for (int r = 0; r < 8; r++) dot += P[i*8 + r] * Qm[j*8 + r];
    float sp = (dot > 20.f) ? dot : log1pf(expf(dot));
    float ad = (a0 > 0.f) ? sp : 0.f;     // mask == (A0 > 0)
    float a  = a0 * (1.f + alphap[0] * ad);
    __shared__ float sbuf[NN];
    sbuf[j] = a;
    __syncthreads();
    for (int st = 32; st >= 1; st >>= 1) {
        if (j < st) sbuf[j] += sbuf[j + st];
        __syncthreads();
    }
    A[i*NN + j] = a / (sbuf[0] + 1e-8f);
}

// ---------------- edge prep: CSR rowptr + logA0 ----------------
__global__ void rowptr_kernel(const int* __restrict__ src, int E, int* __restrict__ rowptr)
{
    int t = threadIdx.x;
    if (t > NN) return;
    int lo = 0, hi = E;
    while (lo < hi) { int mid = (lo + hi) >> 1; if (src[mid] < t) lo = mid + 1; else hi = mid; }
    rowptr[t] = lo;
}

__global__ void edge_kernel(const int* __restrict__ src, const int* __restrict__ dst,
                            const float* __restrict__ A0, int E, float* __restrict__ logA0)
{
    int e = blockIdx.x * blockDim.x + threadIdx.x;
    if (e < E) logA0[e] = logf(A0[src[e]*NN + dst[e]] + 1e-8f);
}

// ---------------- edge-parallel GATv2: block = (src node, bt), warp = head ----------------
__global__ __launch_bounds__(128) void attn_kernel(
    const float* __restrict__ Xq, const float* __restrict__ Xv,
    const float* __restrict__ a_att_l,
    const int* __restrict__ rowptr, const int* __restrict__ dstidx,
    const float* __restrict__ logA0, float* __restrict__ Y)
{
    int i  = blockIdx.x;
    int bt = blockIdx.y;
    int h    = threadIdx.x >> 5;
    int lane = threadIdx.x & 31;

    __shared__ int   sdst[NN];
    __shared__ float slog[NN];
    __shared__ float sexp[HH][NN];

    int e0 = g_rowptr[i], e1 = g_rowptr[i + 1];
    (void)rowptr;
    int deg = e1 - e0;
    for (int k = threadIdx.x; k < deg; k += blockDim.x) {
        sdst[k] = dstidx[e0 + k];
        slog[k] = logA0[e0 + k];
    }
    __syncthreads();

    const float a  = a_att_l[h * DHH + lane];
    const float qi = Xq[((size_t)bt * NN + i) * DD + h * DHH + lane];

    float vmax = -1e30f;
    for (int k = 0; k < deg; k++) {
        int j = sdst[k];
        float x = qi + Xq[((size_t)bt * NN + j) * DD + h * DHH + lane];
        x = (x > 0.f) ? x : 0.2f * x;          // leaky_relu(., 0.2)
        float v = x * a;
        #pragma unroll
        for (int o = 16; o; o >>= 1) v += __shfl_xor_sync(0xffffffffu, v, o);
        v += slog[k];
        sexp[h][k] = v;
        vmax = fmaxf(vmax, v);
    }
    __syncwarp();
    float denom = 0.f;
    for (int k = lane; k < deg; k += 32) {
        float ev = expf(sexp[h][k] - vmax);
        sexp[h][k] = ev;
        denom += ev;
    }
    #pragma unroll
    for (int o = 16; o; o >>= 1) denom += __shfl_xor_sync(0xffffffffu, denom, o);
    __syncwarp();
    float inv = 1.f / denom;

    float y = 0.f;
    for (int k = 0; k < deg; k++) {
        int j = sdst[k];
        y += sexp[h][k] * Xv[((size_t)bt * NN + j) * DD + h * DHH + lane];
    }
    Y[((size_t)bt * NN + i) * DD + h * DHH + lane] = y * inv;
}

// ---------------- outputs ----------------
__global__ void copy_kernel(const float* __restrict__ src, float* __restrict__ dst, int n4)
{
    int i = blockIdx.x * blockDim.x + threadIdx.x;
    if (i < n4) ((float4*)dst)[i] = ((const float4*)src)[i];
}

__global__ void s_kernel(const float* __restrict__ Z, float* __restrict__ S)
{
    int idx = blockIdx.x * blockDim.x + threadIdx.x;
    if (idx >= NBT * DD) return;
    int bt = idx >> 7, d = idx & 127;
    float acc = 0.f;
    for (int n = 0; n < NN; n++) acc += Z[(((size_t)bt * NN) + n) * DD + d];
    S[idx] = acc * (1.f / (float)NN);
}

__global__ void fill0_kernel(float* __restrict__ p, int n)
{
    int i = blockIdx.x * blockDim.x + threadIdx.x;
    if (i < n) p[i] = 0.f;
}

// ---------------- host driver ----------------
static inline void gemm(const float* A, const float* B, float* C, int M, int K, int N,
                        const float* bias, const float* add1, const float* add2, int act)
{
    dim3 g(N / 64, M / 64);
    sgemm_kernel<<<g, 256>>>(A, B, C, M, K, N, bias, add1, add2, act);
}

extern "C" void kernel_launch(void* const* d_in, const int* in_sizes, int n_in,
                              void* d_out, int out_size)
{
    const float* X     = (const float*)d_in[0];
    const float* Wp    = (const float*)d_in[1];
    const float* bp    = (const float*)d_in[2];
    const float* P     = (const float*)d_in[3];
    const float* Qm    = (const float*)d_in[4];
    const float* alpha = (const float*)d_in[5];
    const float* ln1g  = (const float*)d_in[6];
    const float* ln1b  = (const float*)d_in[7];
    const float* Wlin  = (const float*)d_in[8];
    const float* Wval  = (const float*)d_in[9];
    const float* a_att = (const float*)d_in[10];
    const float* Wout  = (const float*)d_in[11];
    const float* g1w   = (const float*)d_in[12];
    const float* g1b   = (const float*)d_in[13];
    const float* g2w   = (const float*)d_in[14];
    const float* g2b   = (const float*)d_in[15];
    const float* ln2g  = (const float*)d_in[16];
    const float* ln2b  = (const float*)d_in[17];
    const float* Wm1   = (const float*)d_in[18];
    const float* bm1   = (const float*)d_in[19];
    const float* Wm2   = (const float*)d_in[20];
    const float* bm2   = (const float*)d_in[21];
    const float* A0    = (const float*)d_in[22];
    // d_in[23] = mask (bool) — intentionally unused; mask == (A0 > 0)
    const int*   srcI  = (const int*)d_in[24];
    const int*   dstI  = (const int*)d_in[25];
    int E = in_sizes[24];
    float* out = (float*)d_out;

    float *Z, *Hn, *Hmix, *Xq, *Xv, *Y, *U, *M1, *A, *logA0;
    int* rowptr;
    cudaGetSymbolAddress((void**)&Z,     g_Z);
    cudaGetSymbolAddress((void**)&Hn,    g_Hn);
    cudaGetSymbolAddress((void**)&Hmix,  g_Hmix);
    cudaGetSymbolAddress((void**)&Xq,    g_Xq);
    cudaGetSymbolAddress((void**)&Xv,    g_Xv);
    cudaGetSymbolAddress((void**)&Y,     g_Y);
    cudaGetSymbolAddress((void**)&U,     g_U);
    cudaGetSymbolAddress((void**)&M1,    g_M1);
    cudaGetSymbolAddress((void**)&A,     g_A);
    cudaGetSymbolAddress((void**)&logA0, g_logA0);
    cudaGetSymbolAddress((void**)&rowptr, g_rowptr);

    // --- setup: adjacency, edge prep, input projection ---
    adj_kernel<<<NN, NN>>>(A0, P, Qm, alpha, A);
    rowptr_kernel<<<1, 128>>>(srcI, E, rowptr);
    edge_kernel<<<(E + 127) / 128, 128>>>(srcI, dstI, A0, E, logA0);
    gemm(X, Wp, Z, NROWS, DD, DD, bp, nullptr, nullptr, 0);   // Z = X@Wp + bp

    const int LN_BLOCKS = NROWS / 8;   // 8 warps per 256-thread block

    for (int l = 0; l < LL; l++) {
        const float* Wlin_l = Wlin + (size_t)l * DD * DD;
        const float* Wval_l = Wval + (size_t)l * DD * DD;
        const float* Wout_l = Wout + (size_t)l * DD * DD;
        const float* Wm1_l  = Wm1  + (size_t)l * DD * D4;
        const float* Wm2_l  = Wm2  + (size_t)l * D4 * DD;

        ln_kernel<<<LN_BLOCKS, 256>>>(Z, Hn, ln1g + l * DD, ln1b + l * DD);

        gemm(Hn, Wlin_l, Xq, NROWS, DD, DD, nullptr, nullptr, nullptr, 0);
        gemm(Hn, Wval_l, Xv, NROWS, DD, DD, nullptr, nullptr, nullptr, 0);
        hmix_kernel<<<NBT, 256>>>(A, Hn, Hmix);

        dim3 ag(NN, NBT);
        attn_kernel<<<ag, 128>>>(Xq, Xv, a_att + l * HH * DHH, rowptr, dstI, logA0, Y);

        // U = Y@Wout + Z + Hmix
        gemm(Y, Wout_l, U, NROWS, DD, DD, nullptr, Z, Hmix, 0);

        // gate + LN2: U <- U*g (in place), Hn <- LN2(U)
        gate_ln2_kernel<<<LN_BLOCKS, 256>>>(U, Hn,
            g1w + l * DD, g1b + l * DD, g2w + l * DD, g2b + l,
            ln2g + l * DD, ln2b + l * DD);

        // MLP: M1 = silu(Hn@Wm1 + bm1); Z = M1@Wm2 + bm2 + U
        gemm(Hn, Wm1_l, M1, NROWS, DD, D4, bm1 + l * D4, nullptr, nullptr, 1);
        gemm(M1, Wm2_l, Z,  NROWS, D4, DD, bm2 + l * DD, U, nullptr, 0);
    }

    // --- outputs: [Zout | S | A] (defensive on out_size) ---
    const int ZN = NROWS * DD;       // 4194304
    const int SN = NBT * DD;         // 65536
    const int AN = NN * NN;          // 4096

    if (out_size >= ZN)
        copy_kernel<<<(ZN / 4 + 255) / 256, 256>>>(Z, out, ZN / 4);
    if (out_size >= ZN + SN)
        s_kernel<<<(SN + 255) / 256, 256>>>(Z, out + ZN);
    if (out_size >= ZN + SN + AN)
        copy_kernel<<<(AN / 4 + 255) / 256, 256>>>(A, out + ZN + SN, AN / 4);
    int tail = out_size - (ZN + SN + AN);
    if (tail > 0)
        fill0_kernel<<<(tail + 255) / 256, 256>>>(out + ZN + SN + AN, tail);
}

// round 3
// speedup vs baseline: 1.7983x; 1.7983x over previous
#include <cuda_runtime.h>
#include <math.h>
#include <stdint.h>

// ---------------- problem constants ----------------
#define BB 4
#define TT 128
#define NBT 512            // B*T
#define NN 64
#define DD 128
#define HH 4
#define DHH 32
#define LL 3
#define D4 512
#define NROWS (NBT*NN)     // 32768
#define MAXE 4096

// ---------------- scratch (device globals; no allocation) ----------------
__device__ float g_Z   [NROWS*DD];
__device__ float g_Hn  [NROWS*DD];
__device__ float g_Hmix[NROWS*DD];
__device__ float g_Xq  [NROWS*DD];
__device__ float g_Xv  [NROWS*DD];
__device__ float g_Y   [NROWS*DD];
__device__ float g_U   [NROWS*DD];
__device__ float g_M1  [NROWS*D4];
__device__ float g_A   [NN*NN];
__device__ float g_logA0[MAXE];
__device__ int   g_rowptr[NN+1];

// ---------------- tf32 tensor-core GEMM ----------------
// C[M,N] = act( A[M,K] @ B[K,N] + bias ) + add1 + add2   (act: 0=none, 1=silu)
// Block tile 128x128, K-tile 16, 256 threads (8 warps as 2m x 4n), double-buffered cp.async.
#define BM 128
#define BN 128
#define BKT 16
#define AST 20    // padded row stride of As (floats): conflict-free fragment reads
#define BST 132   // padded row stride of Bs (floats): <=2-way on fragment reads

__device__ __forceinline__ void cp_async16(void* smem, const void* gmem) {
    unsigned sa = (unsigned)__cvta_generic_to_shared(smem);
    asm volatile("cp.async.cg.shared.global [%0], [%1], 16;\n" :: "r"(sa), "l"(gmem));
}
__device__ __forceinline__ uint32_t f2tf(float x) {
    uint32_t r; asm("cvt.rna.tf32.f32 %0, %1;" : "=r"(r) : "f"(x)); return r;
}
__device__ __forceinline__ void mma_tf32(float* c, const uint32_t* a, const uint32_t* b) {
    asm volatile("mma.sync.aligned.m16n8k8.row.col.f32.tf32.tf32.f32 "
        "{%0,%1,%2,%3}, {%4,%5,%6,%7}, {%8,%9}, {%0,%1,%2,%3};"
        : "+f"(c[0]), "+f"(c[1]), "+f"(c[2]), "+f"(c[3])
        : "r"(a[0]), "r"(a[1]), "r"(a[2]), "r"(a[3]), "r"(b[0]), "r"(b[1]));
}

__global__ __launch_bounds__(256) void tf32gemm_kernel(
    const float* __restrict__ A, const float* __restrict__ B, float* __restrict__ C,
    int M, int K, int N,
    const float* __restrict__ bias, const float* __restrict__ add1,
    const float* __restrict__ add2, int act)
{
    __shared__ float As[2][BM * AST];
    __shared__ float Bs[2][BKT * BST];

    const int tid  = threadIdx.x;
    const int lane = tid & 31;
    const int wid  = tid >> 5;
    const int wm = (wid & 1) * 64;     // warp m-offset within block tile
    const int wn = (wid >> 1) * 32;    // warp n-offset
    const int bm = blockIdx.y * BM;
    const int bn = blockIdx.x * BN;

    const float* Agp = A + (size_t)bm * K;
    const float* Bgp = B + bn;

    // load-thread mapping
    const int arow = tid >> 1;               // 0..127
    const int acol = (tid & 1) * 8;          // 0 or 8
    const int bidx0 = tid * 2;               // B float4 index base (each thread: 2)

    float c[4][4][4];
    #pragma unroll
    for (int mi = 0; mi < 4; mi++)
        #pragma unroll
        for (int ni = 0; ni < 4; ni++)
            #pragma unroll
            for (int q = 0; q < 4; q++) c[mi][ni][q] = 0.f;

    const int ntiles = K / BKT;

    // prologue: stage 0
    {
        cp_async16(&As[0][arow * AST + acol],     Agp + (size_t)arow * K + acol);
        cp_async16(&As[0][arow * AST + acol + 4], Agp + (size_t)arow * K + acol + 4);
        #pragma unroll
        for (int i = 0; i < 2; i++) {
            int idx = bidx0 + i;
            int bk = idx >> 5, bn4 = (idx & 31) * 4;
            cp_async16(&Bs[0][bk * BST + bn4], Bgp + (size_t)bk * N + bn4);
        }
        asm volatile("cp.async.commit_group;\n");
    }

    for (int t = 0; t < ntiles; t++) {
        if (t + 1 < ntiles) {
            const int k0 = (t + 1) * BKT;
            const int buf = (t + 1) & 1;
            cp_async16(&As[buf][arow * AST + acol],     Agp + (size_t)arow * K + k0 + acol);
            cp_async16(&As[buf][arow * AST + acol + 4], Agp + (size_t)arow * K + k0 + acol + 4);
            #pragma unroll
            for (int i = 0; i < 2; i++) {
                int idx = bidx0 + i;
                int bk = idx >> 5, bn4 = (idx & 31) * 4;
                cp_async16(&Bs[buf][bk * BST + bn4], Bgp + (size_t)(k0 + bk) * N + bn4);
            }
            asm volatile("cp.async.commit_group;\n");
            asm volatile("cp.async.wait_group 1;\n");
        } else {
            asm volatile("cp.async.wait_group 0;\n");
        }
        __syncthreads();

        const float* as = As[t & 1];
        const float* bs = Bs[t & 1];
        #pragma unroll
        for (int ks = 0; ks < 2; ks++) {
            uint32_t af[4][4], bf[4][2];
            const int r0 = wm + (lane >> 2);
            const int k0 = ks * 8 + (lane & 3);
            #pragma unroll
            for (int mi = 0; mi < 4; mi++) {
                int rb = (r0 + mi * 16) * AST;
                af[mi][0] = f2tf(as[rb + k0]);
                af[mi][1] = f2tf(as[rb + 8 * AST + k0]);
                af[mi][2] = f2tf(as[rb + k0 + 4]);
                af[mi][3] = f2tf(as[rb + 8 * AST + k0 + 4]);
            }
            const int bn0 = wn + (lane >> 2);
            #pragma unroll
            for (int ni = 0; ni < 4; ni++) {
                bf[ni][0] = f2tf(bs[k0 * BST + bn0 + ni * 8]);
                bf[ni][1] = f2tf(bs[(k0 + 4) * BST + bn0 + ni * 8]);
            }
            #pragma unroll
            for (int mi = 0; mi < 4; mi++)
                #pragma unroll
                for (int ni = 0; ni < 4; ni++)
                    mma_tf32(c[mi][ni], af[mi], bf[ni]);
        }
        __syncthreads();
    }

    // epilogue
    #pragma unroll
    for (int mi = 0; mi < 4; mi++) {
        const int r0 = bm + wm + mi * 16 + (lane >> 2);
        #pragma unroll
        for (int ni = 0; ni < 4; ni++) {
            const int cc = bn + wn + ni * 8 + 2 * (lane & 3);
            float b0 = 0.f, b1 = 0.f;
            if (bias) { b0 = bias[cc]; b1 = bias[cc + 1]; }
            #pragma unroll
            for (int half = 0; half < 2; half++) {
                const int r = r0 + half * 8;
                const size_t ro = (size_t)r * N + cc;
                float v0 = c[mi][ni][half * 2 + 0] + b0;
                float v1 = c[mi][ni][half * 2 + 1] + b1;
                if (act) {
                    v0 = v0 / (1.0f + expf(-v0));
                    v1 = v1 / (1.0f + expf(-v1));
                }
                if (add1) { float2 a = *(const float2*)(add1 + ro); v0 += a.x; v1 += a.y; }
                if (add2) { float2 a = *(const float2*)(add2 + ro); v0 += a.x; v1 += a.y; }
                float2 o; o.x = v0; o.y = v1;
                *(float2*)(C + ro) = o;
            }
        }
    }
}

// ---------------- LayerNorm (warp per row of 128) ----------------
__global__ void ln_kernel(const float* __restrict__ X, float* __restrict__ O,
                          const float* __restrict__ g, const float* __restrict__ b)
{
    int r = blockIdx.x * (blockDim.x >> 5) + (threadIdx.x >> 5);
    if (r >= NROWS) return;
    int lane = threadIdx.x & 31;
    const float* x = X + (size_t)r * DD;
    float v[4], s = 0.f, ss = 0.f;
    #pragma unroll
    for (int q = 0; q < 4; q++) { v[q] = x[lane + 32*q]; s += v[q]; ss += v[q]*v[q]; }
    #pragma unroll
    for (int o = 16; o; o >>= 1) {
        s  += __shfl_xor_sync(0xffffffffu, s,  o);
        ss += __shfl_xor_sync(0xffffffffu, ss, o);
    }
    float mu  = s  * (1.f/128.f);
    float var = ss * (1.f/128.f) - mu * mu;
    float inv = rsqrtf(var + 1e-5f);
    float* o = O + (size_t)r * DD;
    #pragma unroll
    for (int q = 0; q < 4; q++) {
        int d = lane + 32*q;
        o[d] = (v[q] - mu) * inv * g[d] + b[d];
    }
}

// ---------------- NodeGate (squeeze-excite) + LN2 fused, warp per row ----------------
__global__ void gate_ln2_kernel(float* __restrict__ U, float* __restrict__ Out,
    const float* __restrict__ g1w, const float* __restrict__ g1b,
    const float* __restrict__ g2w, const float* __restrict__ g2bp,
    const float* __restrict__ ln2g, const float* __restrict__ ln2b)
{
    int r = blockIdx.x * (blockDim.x >> 5) + (threadIdx.x >> 5);
    if (r >= NROWS) return;
    int lane = threadIdx.x & 31;
    float* u = U + (size_t)r * DD;
    float v[4], s = 0.f, ss = 0.f;
    #pragma unroll
    for (int q = 0; q < 4; q++) { v[q] = u[lane + 32*q]; s += v[q]; ss += v[q]*v[q]; }
    #pragma unroll
    for (int o = 16; o; o >>= 1) {
        s  += __shfl_xor_sync(0xffffffffu, s,  o);
        ss += __shfl_xor_sync(0xffffffffu, ss, o);
    }
    float mu  = s  * (1.f/128.f);
    float var = ss * (1.f/128.f) - mu * mu;
    float acc = 0.f;
    #pragma unroll
    for (int q = 0; q < 4; q++) {
        int d = lane + 32*q;
        float t = mu * g1w[d] + g1b[d];
        acc += (t / (1.f + expf(-t))) * g2w[d];
    }
    #pragma unroll
    for (int o = 16; o; o >>= 1) acc += __shfl_xor_sync(0xffffffffu, acc, o);
    float gate = 1.f / (1.f + expf(-(acc + g2bp[0])));
    float mu2  = mu * gate;
    float inv  = rsqrtf(var * gate * gate + 1e-5f);
    float* o = Out + (size_t)r * DD;
    #pragma unroll
    for (int q = 0; q < 4; q++) {
        int d = lane + 32*q;
        float uv = v[q] * gate;
        u[d] = uv;
        o[d] = (uv - mu2) * inv * ln2g[d] + ln2b[d];
    }
}

// ---------------- Hmix = A @ Hn  (per bt; both tiles in smem) ----------------
__global__ __launch_bounds__(256) void hmix_kernel(const float* __restrict__ A,
                                                   const float* __restrict__ Hn,
                                                   float* __restrict__ Hmix)
{
    __shared__ float sA[NN*NN];
    __shared__ float sH[NN*DD];
    int bt = blockIdx.x;
    for (int t = threadIdx.x; t < NN*NN; t += blockDim.x) sA[t] = A[t];
    const float* Hb = Hn + (size_t)bt * NN * DD;
    for (int t = threadIdx.x; t < NN*DD; t += blockDim.x) sH[t] = Hb[t];
    __syncthreads();
    int d  = threadIdx.x & 127;
    for (int i = threadIdx.x >> 7; i < NN; i += 2) {
        float acc = 0.f;
        #pragma unroll 8
        for (int j = 0; j < NN; j++) acc += sA[i*NN + j] * sH[j*DD + d];
        Hmix[((size_t)bt * NN + i) * DD + d] = acc;
    }
}

// ---------------- blended adjacency A ----------------
__global__ void adj_kernel(const float* __restrict__ A0, const float* __restrict__ P,
                           const float* __restrict__ Qm, const float* __restrict__ alphap,
                           float* __restrict__ A)
{
    int i = blockIdx.x, j = threadIdx.x;
    float a0 = A0[i*NN + j];
    float dot = 0.f;
    #pragma unroll
    for (int r = 0; r < 8; r++) dot += P[i*8 + r] * Qm[j*8 + r];
    float sp = (dot > 20.f) ? dot : log1pf(expf(dot));
    float ad = (a0 > 0.f) ? sp : 0.f;
    float a  = a0 * (1.f + alphap[0] * ad);
    __shared__ float sbuf[NN];
    sbuf[j] = a;
    __syncthreads();
    for (int st = 32; st >= 1; st >>= 1) {
        if (j < st) sbuf[j] += sbuf[j + st];
        __syncthreads();
    }
    A[i*NN + j] = a / (sbuf[0] + 1e-8f);
}

// ---------------- edge prep: CSR rowptr + logA0 ----------------
__global__ void rowptr_kernel(const int* __restrict__ src, int E, int* __restrict__ rowptr)
{
    int t = threadIdx.x;
    if (t > NN) return;
    int lo = 0, hi = E;
    while (lo < hi) { int mid = (lo + hi) >> 1; if (src[mid] < t) lo = mid + 1; else hi = mid; }
    rowptr[t] = lo;
}

__global__ void edge_kernel(const int* __restrict__ src, const int* __restrict__ dst,
                            const float* __restrict__ A0, int E, float* __restrict__ logA0)
{
    int e = blockIdx.x * blockDim.x + threadIdx.x;
    if (e < E) logA0[e] = logf(A0[src[e]*NN + dst[e]] + 1e-8f);
}

// ---------------- edge-parallel GATv2: block = (src node, bt), warp = head ----------------
__global__ __launch_bounds__(128) void attn_kernel(
    const float* __restrict__ Xq, const float* __restrict__ Xv,
    const float* __restrict__ a_att_l,
    const int* __restrict__ dstidx,
    const float* __restrict__ logA0, float* __restrict__ Y)
{
    int i  = blockIdx.x;
    int bt = blockIdx.y;
    int h    = threadIdx.x >> 5;
    int lane = threadIdx.x & 31;

    __shared__ int   sdst[NN];
    __shared__ float slog[NN];
    __shared__ float sexp[HH][NN];

    int e0 = g_rowptr[i], e1 = g_rowptr[i + 1];
    int deg = e1 - e0;
    for (int k = threadIdx.x; k < deg; k += blockDim.x) {
        sdst[k] = dstidx[e0 + k];
        slog[k] = logA0[e0 + k];
    }
    __syncthreads();

    const float a  = a_att_l[h * DHH + lane];
    const float qi = Xq[((size_t)bt * NN + i) * DD + h * DHH + lane];

    float vmax = -1e30f;
    for (int k = 0; k < deg; k++) {
        int j = sdst[k];
        float x = qi + Xq[((size_t)bt * NN + j) * DD + h * DHH + lane];
        x = (x > 0.f) ? x : 0.2f * x;
        float v = x * a;
        #pragma unroll
        for (int o = 16; o; o >>= 1) v += __shfl_xor_sync(0xffffffffu, v, o);
        v += slog[k];
        sexp[h][k] = v;
        vmax = fmaxf(vmax, v);
    }
    __syncwarp();
    float denom = 0.f;
    for (int k = lane; k < deg; k += 32) {
        float ev = expf(sexp[h][k] - vmax);
        sexp[h][k] = ev;
        denom += ev;
    }
    #pragma unroll
    for (int o = 16; o; o >>= 1) denom += __shfl_xor_sync(0xffffffffu, denom, o);
    __syncwarp();
    float inv = 1.f / denom;

    float y = 0.f;
    for (int k = 0; k < deg; k++) {
        int j = sdst[k];
        y += sexp[h][k] * Xv[((size_t)bt * NN + j) * DD + h * DHH + lane];
    }
    Y[((size_t)bt * NN + i) * DD + h * DHH + lane] = y * inv;
}

// ---------------- outputs ----------------
__global__ void copy_kernel(const float* __restrict__ src, float* __restrict__ dst, int n4)
{
    int i = blockIdx.x * blockDim.x + threadIdx.x;
    if (i < n4) ((float4*)dst)[i] = ((const float4*)src)[i];
}

__global__ void s_kernel(const float* __restrict__ Z, float* __restrict__ S)
{
    int idx = blockIdx.x * blockDim.x + threadIdx.x;
    if (idx >= NBT * DD) return;
    int bt = idx >> 7, d = idx & 127;
    float acc = 0.f;
    for (int n = 0; n < NN; n++) acc += Z[(((size_t)bt * NN) + n) * DD + d];
    S[idx] = acc * (1.f / (float)NN);
}

__global__ void fill0_kernel(float* __restrict__ p, int n)
{
    int i = blockIdx.x * blockDim.x + threadIdx.x;
    if (i < n) p[i] = 0.f;
}

// ---------------- host driver ----------------
static inline void gemm(const float* A, const float* B, float* C, int M, int K, int N,
                        const float* bias, const float* add1, const float* add2, int act)
{
    dim3 g(N / BN, M / BM);
    tf32gemm_kernel<<<g, 256>>>(A, B, C, M, K, N, bias, add1, add2, act);
}

extern "C" void kernel_launch(void* const* d_in, const int* in_sizes, int n_in,
                              void* d_out, int out_size)
{
    const float* X     = (const float*)d_in[0];
    const float* Wp    = (const float*)d_in[1];
    const float* bp    = (const float*)d_in[2];
    const float* P     = (const float*)d_in[3];
    const float* Qm    = (const float*)d_in[4];
    const float* alpha = (const float*)d_in[5];
    const float* ln1g  = (const float*)d_in[6];
    const float* ln1b  = (const float*)d_in[7];
    const float* Wlin  = (const float*)d_in[8];
    const float* Wval  = (const float*)d_in[9];
    const float* a_att = (const float*)d_in[10];
    const float* Wout  = (const float*)d_in[11];
    const float* g1w   = (const float*)d_in[12];
    const float* g1b   = (const float*)d_in[13];
    const float* g2w   = (const float*)d_in[14];
    const float* g2b   = (const float*)d_in[15];
    const float* ln2g  = (const float*)d_in[16];
    const float* ln2b  = (const float*)d_in[17];
    const float* Wm1   = (const float*)d_in[18];
    const float* bm1   = (const float*)d_in[19];
    const float* Wm2   = (const float*)d_in[20];
    const float* bm2   = (const float*)d_in[21];
    const float* A0    = (const float*)d_in[22];
    const int*   srcI  = (const int*)d_in[24];
    const int*   dstI  = (const int*)d_in[25];
    int E = in_sizes[24];
    float* out = (float*)d_out;

    float *Z, *Hn, *Hmix, *Xq, *Xv, *Y, *U, *M1, *A, *logA0;
    int* rowptr;
    cudaGetSymbolAddress((void**)&Z,     g_Z);
    cudaGetSymbolAddress((void**)&Hn,    g_Hn);
    cudaGetSymbolAddress((void**)&Hmix,  g_Hmix);
    cudaGetSymbolAddress((void**)&Xq,    g_Xq);
    cudaGetSymbolAddress((void**)&Xv,    g_Xv);
    cudaGetSymbolAddress((void**)&Y,     g_Y);
    cudaGetSymbolAddress((void**)&U,     g_U);
    cudaGetSymbolAddress((void**)&M1,    g_M1);
    cudaGetSymbolAddress((void**)&A,     g_A);
    cudaGetSymbolAddress((void**)&logA0, g_logA0);
    cudaGetSymbolAddress((void**)&rowptr, g_rowptr);

    const int ZN = NROWS * DD;       // 4194304
    const int SN = NBT * DD;         // 65536
    const int AN = NN * NN;          // 4096
    float* Zfinal = (out_size >= ZN) ? out : Z;  // last layer writes Z straight to out

    // --- setup ---
    adj_kernel<<<NN, NN>>>(A0, P, Qm, alpha, A);
    rowptr_kernel<<<1, 128>>>(srcI, E, rowptr);
    edge_kernel<<<(E + 127) / 128, 128>>>(srcI, dstI, A0, E, logA0);
    gemm(X, Wp, Z, NROWS, DD, DD, bp, nullptr, nullptr, 0);

    const int LN_BLOCKS = NROWS / 8;

    for (int l = 0; l < LL; l++) {
        const float* Wlin_l = Wlin + (size_t)l * DD * DD;
        const float* Wval_l = Wval + (size_t)l * DD * DD;
        const float* Wout_l = Wout + (size_t)l * DD * DD;
        const float* Wm1_l  = Wm1  + (size_t)l * DD * D4;
        const float* Wm2_l  = Wm2  + (size_t)l * D4 * DD;

        ln_kernel<<<LN_BLOCKS, 256>>>(Z, Hn, ln1g + l * DD, ln1b + l * DD);

        gemm(Hn, Wlin_l, Xq, NROWS, DD, DD, nullptr, nullptr, nullptr, 0);
        gemm(Hn, Wval_l, Xv, NROWS, DD, DD, nullptr, nullptr, nullptr, 0);
        hmix_kernel<<<NBT, 256>>>(A, Hn, Hmix);

        dim3 ag(NN, NBT);
        attn_kernel<<<ag, 128>>>(Xq, Xv, a_att + l * HH * DHH, dstI, logA0, Y);

        gemm(Y, Wout_l, U, NROWS, DD, DD, nullptr, Z, Hmix, 0);

        gate_ln2_kernel<<<LN_BLOCKS, 256>>>(U, Hn,
            g1w + l * DD, g1b + l * DD, g2w + l * DD, g2b + l,
            ln2g + l * DD, ln2b + l * DD);

        float* Ztgt = (l == LL - 1) ? Zfinal : Z;
        gemm(Hn, Wm1_l, M1, NROWS, DD, D4, bm1 + l * D4, nullptr, nullptr, 1);
        gemm(M1, Wm2_l, Ztgt, NROWS, D4, DD, bm2 + l * DD, U, nullptr, 0);
    }

    // --- outputs: [Zout | S | A] ---
    if (out_size >= ZN && Zfinal != out)
        copy_kernel<<<(ZN / 4 + 255) / 256, 256>>>(Z, out, ZN / 4);
    if (out_size >= ZN + SN)
        s_kernel<<<(SN + 255) / 256, 256>>>(Zfinal, out + ZN);
    if (out_size >= ZN + SN + AN)
        copy_kernel<<<(AN / 4 + 255) / 256, 256>>>(A, out + ZN + SN, AN / 4);
    int tail = out_size - (ZN + SN + AN);
    if (tail > 0)
        fill0_kernel<<<(tail + 255) / 256, 256>>>(out + ZN + SN + AN, tail);
}